// round 2
// baseline (speedup 1.0000x reference)
#include <cuda_runtime.h>
#include <math.h>

// Problem constants
#define B_    32
#define CIN   512
#define H_    38
#define W_    38
#define P_    (H_ * W_)      // 1444 pixels per image
#define NA_   3
#define NO_   255            // NA * (NC+5)
#define STRIDE_F 16.0f

// Tiling
#define TP 128   // pixels per block tile
#define TO 64    // out-channels per block tile
#define TK 16    // K chunk

__constant__ float c_anchor_w[NA_] = {30.0f, 62.0f, 59.0f};
__constant__ float c_anchor_h[NA_] = {61.0f, 45.0f, 119.0f};

__global__ __launch_bounds__(256, 2)
void yolo_gemm_decode(const float* __restrict__ xin,
                      const float* __restrict__ wgt,
                      const float* __restrict__ bias,
                      float* __restrict__ out)
{
    __shared__ float As[TK][TP];   // [k][pixel]   8 KB
    __shared__ float Bs[TK][TO];   // [k][outch]   4 KB

    const int b  = blockIdx.z;
    const int p0 = blockIdx.x * TP;
    const int o0 = blockIdx.y * TO;
    const int tid = threadIdx.x;

    // register fragment mapping: 16 thread-groups along pixels (8 px each),
    // 16 along out-channels (4 ch each)
    const int tp = tid & 15;   // pixel group
    const int to = tid >> 4;   // outch group

    const float* xb = xin + (size_t)b * CIN * P_;

    float acc[8][4];
#pragma unroll
    for (int i = 0; i < 8; i++)
#pragma unroll
        for (int j = 0; j < 4; j++) acc[i][j] = 0.0f;

    for (int k0 = 0; k0 < CIN; k0 += TK) {
        // ---- load A tile: TK x TP floats = 512 float4, 2 per thread ----
#pragma unroll
        for (int l = 0; l < 2; l++) {
            int idx  = tid + l * 256;        // 0..511
            int row  = idx >> 5;             // 0..15 (k within chunk)
            int col4 = idx & 31;             // float4 column
            int p    = p0 + col4 * 4;
            float4 v;
            if (p + 3 < P_) {
                v = *reinterpret_cast<const float4*>(xb + (size_t)(k0 + row) * P_ + p);
            } else {
                const float* src = xb + (size_t)(k0 + row) * P_ + p;
                float t0 = (p + 0 < P_) ? src[0] : 0.0f;
                float t1 = (p + 1 < P_) ? src[1] : 0.0f;
                float t2 = (p + 2 < P_) ? src[2] : 0.0f;
                float t3 = (p + 3 < P_) ? src[3] : 0.0f;
                v = make_float4(t0, t1, t2, t3);
            }
            *reinterpret_cast<float4*>(&As[row][col4 * 4]) = v;
        }

        // ---- load B tile: TO x TK floats = 256 float4, 1 per thread, transposed store ----
        {
            int olocal = tid >> 2;            // 0..63
            int o      = o0 + olocal;
            int kq     = (tid & 3) * 4;       // 0,4,8,12
            float4 v = make_float4(0.f, 0.f, 0.f, 0.f);
            if (o < NO_) {
                v = *reinterpret_cast<const float4*>(wgt + (size_t)o * CIN + k0 + kq);
            }
            Bs[kq + 0][olocal] = v.x;
            Bs[kq + 1][olocal] = v.y;
            Bs[kq + 2][olocal] = v.z;
            Bs[kq + 3][olocal] = v.w;
        }

        __syncthreads();

        // ---- MAC loop ----
#pragma unroll
        for (int k = 0; k < TK; k++) {
            float a[8], bb[4];
#pragma unroll
            for (int i = 0; i < 8; i++) a[i] = As[k][tp * 8 + i];
#pragma unroll
            for (int j = 0; j < 4; j++) bb[j] = Bs[k][to * 4 + j];
#pragma unroll
            for (int i = 0; i < 8; i++)
#pragma unroll
                for (int j = 0; j < 4; j++)
                    acc[i][j] = fmaf(a[i], bb[j], acc[i][j]);
        }

        __syncthreads();
    }

    // ---- fused YOLO decode epilogue ----
#pragma unroll
    for (int j = 0; j < 4; j++) {
        int o = o0 + to * 4 + j;
        if (o >= NO_) continue;
        float bv   = bias[o];
        int a_idx  = o / 85;
        int e      = o - a_idx * 85;
#pragma unroll
        for (int i = 0; i < 8; i++) {
            int p = p0 + tp * 8 + i;
            if (p >= P_) continue;
            float v = acc[i][j] + bv;
            float r;
            if (e == 0) {
                float xoff = (float)(p % W_);
                r = (1.0f / (1.0f + expf(-v)) + xoff) * STRIDE_F;
            } else if (e == 1) {
                float yoff = (float)(p / W_);
                r = (1.0f / (1.0f + expf(-v)) + yoff) * STRIDE_F;
            } else if (e == 2) {
                r = expf(v) * c_anchor_w[a_idx];
            } else if (e == 3) {
                r = expf(v) * c_anchor_h[a_idx];
            } else {
                r = v;
            }
            out[((size_t)b * P_ + p) * NO_ + o] = r;
        }
    }
}

extern "C" void kernel_launch(void* const* d_in, const int* in_sizes, int n_in,
                              void* d_out, int out_size)
{
    const float* xin  = (const float*)d_in[0];
    const float* wgt  = (const float*)d_in[1];
    const float* bias = (const float*)d_in[2];
    float* out = (float*)d_out;

    dim3 grid((P_ + TP - 1) / TP,   // 12
              (NO_ + TO - 1) / TO,  // 4
              B_);                  // 32
    yolo_gemm_decode<<<grid, 256>>>(xin, wgt, bias, out);
}

// round 6
// speedup vs baseline: 3.5700x; 3.5700x over previous
#include <cuda_runtime.h>
#include <math.h>
#include <stdint.h>

// ---------------- problem constants ----------------
#define B_    32
#define CIN   512
#define H_    38
#define W_    38
#define P_    1444          // 38*38, divisible by 4
#define NO_   255
#define STRIDE_F 16.0f

// ---------------- tiling ----------------
#define TM      128         // pixels per CTA
#define TN      256         // all out-channels (255 padded)
#define KC      32          // k per chunk
#define NCHUNK  (CIN / KC)  // 16
#define STAGES  3

// smem strides (floats) chosen for conflict-free access
#define A_LD    136         // A_sm[k][A_LD], k=0..31, m=0..127
#define B_LD    36          // B_sm[n][B_LD], n=0..255, k=0..31
#define A_BYTES (KC * A_LD * 4)          // 17408
#define B_BYTES (TN * B_LD * 4)          // 36864
#define STAGE_BYTES (A_BYTES + B_BYTES)  // 54272
#define SMEM_TOTAL  (STAGE_BYTES * STAGES) // 162816

__constant__ float c_aw[3] = {30.0f, 62.0f, 59.0f};
__constant__ float c_ah[3] = {61.0f, 45.0f, 119.0f};

static __device__ __forceinline__ uint32_t smem_u32(const void* p) {
    uint32_t a;
    asm("{ .reg .u64 t; cvta.to.shared.u64 t, %1; cvt.u32.u64 %0, t; }" : "=r"(a) : "l"(p));
    return a;
}
static __device__ __forceinline__ uint32_t f2tf32(float f) {
    uint32_t r;
    asm("cvt.rna.tf32.f32 %0, %1;" : "=r"(r) : "f"(f));
    return r;
}
static __device__ __forceinline__ void cp_async16(uint32_t dst, const void* src, bool pred) {
    int sz = pred ? 16 : 0;
    asm volatile("cp.async.cg.shared.global [%0], [%1], 16, %2;"
                 :: "r"(dst), "l"(src), "r"(sz));
}
#define CP_COMMIT() asm volatile("cp.async.commit_group;" ::: "memory")
#define CP_WAIT1()  asm volatile("cp.async.wait_group 1;" ::: "memory")

static __device__ __forceinline__ void mma_tf32(float c[4], const uint32_t a[4],
                                                const uint32_t b[2]) {
    asm volatile(
        "mma.sync.aligned.m16n8k8.row.col.f32.tf32.tf32.f32 "
        "{%0,%1,%2,%3}, {%4,%5,%6,%7}, {%8,%9}, {%0,%1,%2,%3};"
        : "+f"(c[0]), "+f"(c[1]), "+f"(c[2]), "+f"(c[3])
        : "r"(a[0]), "r"(a[1]), "r"(a[2]), "r"(a[3]), "r"(b[0]), "r"(b[1]));
}

__global__ __launch_bounds__(256, 1)
void yolo_mma_tf32(const float* __restrict__ xin, const float* __restrict__ wgt,
                   const float* __restrict__ bias, float* __restrict__ out)
{
    extern __shared__ char smem[];
    const uint32_t sbase = smem_u32(smem);
    const int tid  = threadIdx.x;
    const int wid  = tid >> 5;
    const int lane = tid & 31;
    const int g    = lane >> 2;   // groupID (rows)
    const int t4   = lane & 3;    // thread-in-group (cols)
    const int p0   = blockIdx.x * TM;
    const int b    = blockIdx.y;
    const float* xb = xin + (size_t)b * CIN * P_;

    const int wm = (wid & 1) * 64;   // warp m base within tile
    const int wn = (wid >> 1) * 64;  // warp n base

    float acc[4][8][4];
#pragma unroll
    for (int mt = 0; mt < 4; mt++)
#pragma unroll
        for (int nt = 0; nt < 8; nt++)
#pragma unroll
            for (int q = 0; q < 4; q++) acc[mt][nt][q] = 0.0f;

    // ---------------- async loader ----------------
    auto issue_chunk = [&](int chunk, int stage) {
        const uint32_t abase = sbase + stage * STAGE_BYTES;
        const uint32_t bbase = abase + A_BYTES;
        const int k0 = chunk * KC;
        // A: 1024 float4 (32 k-rows x 32 float4), coalesced 512B per warp
#pragma unroll
        for (int j = 0; j < 4; j++) {
            int idx = tid + j * 256;
            int k = idx >> 5;
            int m = (idx & 31) * 4;
            bool pred = (p0 + m) < P_;
            const float* src = xb + (size_t)(k0 + k) * P_ + p0 + m;
            if (!pred) src = xb;   // keep address valid; 0 bytes copied
            cp_async16(abase + (uint32_t)(k * A_LD + m) * 4, src, pred);
        }
        // B: 2048 float4 (256 n-rows x 8 float4)
#pragma unroll
        for (int j = 0; j < 8; j++) {
            int idx = tid + j * 256;
            int n = idx >> 3;
            int kq = (idx & 7) * 4;
            bool pred = n < NO_;
            const float* src = wgt + (size_t)n * CIN + k0 + kq;
            if (!pred) src = wgt;
            cp_async16(bbase + (uint32_t)(n * B_LD + kq) * 4, src, pred);
        }
    };

    // prologue: stages 0,1
    issue_chunk(0, 0); CP_COMMIT();
    issue_chunk(1, 1); CP_COMMIT();

    for (int i = 0; i < NCHUNK; i++) {
        const int st = i % STAGES;
        CP_WAIT1();          // chunk i resident
        __syncthreads();     // all warps past chunk i-1 (frees buffer (i+2)%3)
        if (i + 2 < NCHUNK) issue_chunk(i + 2, (i + 2) % STAGES);
        CP_COMMIT();         // uniform group count (empty group ok)

        const float* A  = (const float*)(smem + (size_t)st * STAGE_BYTES);
        const float* Bm = (const float*)(smem + (size_t)st * STAGE_BYTES + A_BYTES);

#pragma unroll
        for (int ks = 0; ks < 4; ks++) {
            const int kb = ks * 8;
            uint32_t af[4][4], bf[8][2];
#pragma unroll
            for (int mt = 0; mt < 4; mt++) {
                const int mb = wm + mt * 16;
                af[mt][0] = f2tf32(A[(kb + t4) * A_LD + mb + g]);
                af[mt][1] = f2tf32(A[(kb + t4) * A_LD + mb + g + 8]);
                af[mt][2] = f2tf32(A[(kb + t4 + 4) * A_LD + mb + g]);
                af[mt][3] = f2tf32(A[(kb + t4 + 4) * A_LD + mb + g + 8]);
            }
#pragma unroll
            for (int nt = 0; nt < 8; nt++) {
                const int nb = wn + nt * 8 + g;
                bf[nt][0] = f2tf32(Bm[nb * B_LD + kb + t4]);
                bf[nt][1] = f2tf32(Bm[nb * B_LD + kb + t4 + 4]);
            }
#pragma unroll
            for (int mt = 0; mt < 4; mt++)
#pragma unroll
                for (int nt = 0; nt < 8; nt++)
                    mma_tf32(acc[mt][nt], af[mt], bf[nt]);
        }
    }

    // ---------------- fused YOLO decode epilogue ----------------
#pragma unroll
    for (int mt = 0; mt < 4; mt++) {
        const int r0 = wm + mt * 16 + g;   // local row, +8 for second half
#pragma unroll
        for (int half = 0; half < 2; half++) {
            const int p = p0 + r0 + half * 8;
            if (p >= P_) continue;
            const float xo = (float)(p % W_);
            const float yo = (float)(p / W_);
            const size_t obase = ((size_t)b * P_ + p) * NO_;
#pragma unroll
            for (int nt = 0; nt < 8; nt++) {
#pragma unroll
                for (int q = 0; q < 2; q++) {
                    const int o = wn + nt * 8 + t4 * 2 + q;
                    if (o >= NO_) continue;
                    float v = acc[mt][nt][half * 2 + q] + __ldg(bias + o);
                    const int ai = (o >= 170) ? 2 : ((o >= 85) ? 1 : 0);
                    const int e = o - ai * 85;
                    float res;
                    if (e >= 4)      res = v;
                    else if (e == 0) res = (1.0f / (1.0f + __expf(-v)) + xo) * STRIDE_F;
                    else if (e == 1) res = (1.0f / (1.0f + __expf(-v)) + yo) * STRIDE_F;
                    else if (e == 2) res = __expf(v) * c_aw[ai];
                    else             res = __expf(v) * c_ah[ai];
                    out[obase + o] = res;
                }
            }
        }
    }
}

extern "C" void kernel_launch(void* const* d_in, const int* in_sizes, int n_in,
                              void* d_out, int out_size)
{
    const float* xin  = (const float*)d_in[0];
    const float* wgt  = (const float*)d_in[1];
    const float* bias = (const float*)d_in[2];
    float* out = (float*)d_out;

    cudaFuncSetAttribute(yolo_mma_tf32, cudaFuncAttributeMaxDynamicSharedMemorySize,
                         SMEM_TOTAL);
    dim3 grid((P_ + TM - 1) / TM, B_);   // 12 x 32 = 384 CTAs
    yolo_mma_tf32<<<grid, 256, SMEM_TOTAL>>>(xin, wgt, bias, out);
}

// round 7
// speedup vs baseline: 4.0876x; 1.1450x over previous
#include <cuda_runtime.h>
#include <math.h>
#include <stdint.h>

// ---------------- problem constants ----------------
#define B_    32
#define CIN   512
#define H_    38
#define W_    38
#define P_    1444          // 38*38
#define NO_   255
#define STRIDE_F 16.0f

// ---------------- tiling ----------------
#define TM      128         // pixels per CTA
#define TN      128         // out-channels per CTA (2 CTAs cover 256)
#define KC      32          // k per chunk
#define NCHUNK  (CIN / KC)  // 16
#define STAGES  3

// smem strides (floats) chosen for conflict-free access
#define A_LD    136         // A_sm[k][A_LD]; 136 % 32 == 8 -> frag bank = t4*8+g (distinct)
#define B_LD    36          // B_sm[n][B_LD]; 36 % 32 == 4  -> frag bank = g*4+t4 (distinct)
#define A_BYTES (KC * A_LD * 4)            // 17408
#define B_BYTES (TN * B_LD * 4)            // 18432
#define STAGE_BYTES (A_BYTES + B_BYTES)    // 35840
#define SMEM_TOTAL  (STAGE_BYTES * STAGES) // 107520  (fits 2 CTAs in 227KB)

__constant__ float c_aw[3] = {30.0f, 62.0f, 59.0f};
__constant__ float c_ah[3] = {61.0f, 45.0f, 119.0f};

static __device__ __forceinline__ uint32_t smem_u32(const void* p) {
    uint32_t a;
    asm("{ .reg .u64 t; cvta.to.shared.u64 t, %1; cvt.u32.u64 %0, t; }" : "=r"(a) : "l"(p));
    return a;
}
static __device__ __forceinline__ uint32_t f2tf32(float f) {
    uint32_t r;
    asm("cvt.rna.tf32.f32 %0, %1;" : "=r"(r) : "f"(f));   // rna = unbiased; truncation would
    return r;                                             // bias result ~1e-3 (fails gate)
}
static __device__ __forceinline__ void cp_async16(uint32_t dst, const void* src, bool pred) {
    int sz = pred ? 16 : 0;
    asm volatile("cp.async.cg.shared.global [%0], [%1], 16, %2;"
                 :: "r"(dst), "l"(src), "r"(sz));
}
#define CP_COMMIT() asm volatile("cp.async.commit_group;" ::: "memory")
#define CP_WAIT1()  asm volatile("cp.async.wait_group 1;" ::: "memory")

static __device__ __forceinline__ void mma_tf32(float c[4], const uint32_t a[4],
                                                const uint32_t b[2]) {
    asm volatile(
        "mma.sync.aligned.m16n8k8.row.col.f32.tf32.tf32.f32 "
        "{%0,%1,%2,%3}, {%4,%5,%6,%7}, {%8,%9}, {%0,%1,%2,%3};"
        : "+f"(c[0]), "+f"(c[1]), "+f"(c[2]), "+f"(c[3])
        : "r"(a[0]), "r"(a[1]), "r"(a[2]), "r"(a[3]), "r"(b[0]), "r"(b[1]));
}

__global__ __launch_bounds__(256, 2)
void yolo_mma_tf32(const float* __restrict__ xin, const float* __restrict__ wgt,
                   const float* __restrict__ bias, float* __restrict__ out)
{
    extern __shared__ char smem[];
    const uint32_t sbase = smem_u32(smem);
    const int tid  = threadIdx.x;
    const int wid  = tid >> 5;
    const int lane = tid & 31;
    const int g    = lane >> 2;   // groupID (rows)
    const int t4   = lane & 3;    // thread-in-group (cols)
    const int p0   = blockIdx.x * TM;
    const int n0   = blockIdx.y * TN;
    const int b    = blockIdx.z;
    const float* xb = xin + (size_t)b * CIN * P_;

    const int wm = (wid & 3) * 32;   // warp m base within tile (4 m-groups)
    const int wn = (wid >> 2) * 64;  // warp n base within tile (2 n-groups)

    float acc[2][8][4];
#pragma unroll
    for (int mt = 0; mt < 2; mt++)
#pragma unroll
        for (int nt = 0; nt < 8; nt++)
#pragma unroll
            for (int q = 0; q < 4; q++) acc[mt][nt][q] = 0.0f;

    // ---------------- async loader ----------------
    auto issue_chunk = [&](int chunk, int stage) {
        const uint32_t abase = sbase + stage * STAGE_BYTES;
        const uint32_t bbase = abase + A_BYTES;
        const int k0 = chunk * KC;
        // A: 1024 float4 (32 k-rows x 32 float4), coalesced 512B per warp
#pragma unroll
        for (int j = 0; j < 4; j++) {
            int idx = tid + j * 256;
            int k = idx >> 5;
            int m = (idx & 31) * 4;
            bool pred = (p0 + m) < P_;
            const float* src = xb + (size_t)(k0 + k) * P_ + p0 + m;
            if (!pred) src = xb;   // keep address valid; 0 bytes copied
            cp_async16(abase + (uint32_t)(k * A_LD + m) * 4, src, pred);
        }
        // B: 1024 float4 (128 n-rows x 8 float4)
#pragma unroll
        for (int j = 0; j < 4; j++) {
            int idx = tid + j * 256;
            int n = idx >> 3;             // local n 0..127
            int kq = (idx & 7) * 4;
            int gn = n0 + n;
            bool pred = gn < NO_;
            const float* src = wgt + (size_t)gn * CIN + k0 + kq;
            if (!pred) src = wgt;
            cp_async16(bbase + (uint32_t)(n * B_LD + kq) * 4, src, pred);
        }
    };

    // prologue: stages 0,1
    issue_chunk(0, 0); CP_COMMIT();
    issue_chunk(1, 1); CP_COMMIT();

    for (int i = 0; i < NCHUNK; i++) {
        const int st = i % STAGES;
        CP_WAIT1();          // chunk i resident
        __syncthreads();     // all warps done with chunk i-1 (frees buffer (i+2)%3)
        if (i + 2 < NCHUNK) issue_chunk(i + 2, (i + 2) % STAGES);
        CP_COMMIT();         // uniform group count (empty group ok)

        const float* A  = (const float*)(smem + (size_t)st * STAGE_BYTES);
        const float* Bm = (const float*)(smem + (size_t)st * STAGE_BYTES + A_BYTES);

#pragma unroll
        for (int ks = 0; ks < 4; ks++) {
            const int kb = ks * 8;
            uint32_t af[2][4], bf[8][2];
#pragma unroll
            for (int mt = 0; mt < 2; mt++) {
                const int mb = wm + mt * 16;
                af[mt][0] = f2tf32(A[(kb + t4) * A_LD + mb + g]);
                af[mt][1] = f2tf32(A[(kb + t4) * A_LD + mb + g + 8]);
                af[mt][2] = f2tf32(A[(kb + t4 + 4) * A_LD + mb + g]);
                af[mt][3] = f2tf32(A[(kb + t4 + 4) * A_LD + mb + g + 8]);
            }
#pragma unroll
            for (int nt = 0; nt < 8; nt++) {
                const int nb = wn + nt * 8 + g;
                bf[nt][0] = f2tf32(Bm[nb * B_LD + kb + t4]);
                bf[nt][1] = f2tf32(Bm[nb * B_LD + kb + t4 + 4]);
            }
#pragma unroll
            for (int mt = 0; mt < 2; mt++)
#pragma unroll
                for (int nt = 0; nt < 8; nt++)
                    mma_tf32(acc[mt][nt], af[mt], bf[nt]);
        }
    }

    // ---------------- fused YOLO decode epilogue ----------------
#pragma unroll
    for (int mt = 0; mt < 2; mt++) {
        const int r0 = wm + mt * 16 + g;   // local row, +8 for second half
#pragma unroll
        for (int half = 0; half < 2; half++) {
            const int p = p0 + r0 + half * 8;
            if (p >= P_) continue;
            const float xo = (float)(p % W_);
            const float yo = (float)(p / W_);
            const size_t obase = ((size_t)b * P_ + p) * NO_;
#pragma unroll
            for (int nt = 0; nt < 8; nt++) {
#pragma unroll
                for (int q = 0; q < 2; q++) {
                    const int o = n0 + wn + nt * 8 + t4 * 2 + q;
                    if (o >= NO_) continue;
                    float v = acc[mt][nt][half * 2 + q] + __ldg(bias + o);
                    const int ai = (o >= 170) ? 2 : ((o >= 85) ? 1 : 0);
                    const int e = o - ai * 85;
                    float res;
                    if (e >= 4)      res = v;
                    else if (e == 0) res = (1.0f / (1.0f + __expf(-v)) + xo) * STRIDE_F;
                    else if (e == 1) res = (1.0f / (1.0f + __expf(-v)) + yo) * STRIDE_F;
                    else if (e == 2) res = __expf(v) * c_aw[ai];
                    else             res = __expf(v) * c_ah[ai];
                    out[obase + o] = res;
                }
            }
        }
    }
}

extern "C" void kernel_launch(void* const* d_in, const int* in_sizes, int n_in,
                              void* d_out, int out_size)
{
    const float* xin  = (const float*)d_in[0];
    const float* wgt  = (const float*)d_in[1];
    const float* bias = (const float*)d_in[2];
    float* out = (float*)d_out;

    cudaFuncSetAttribute(yolo_mma_tf32, cudaFuncAttributeMaxDynamicSharedMemorySize,
                         SMEM_TOTAL);
    dim3 grid((P_ + TM - 1) / TM, 2, B_);   // 12 x 2 x 32 = 768 CTAs
    yolo_mma_tf32<<<grid, 256, SMEM_TOTAL>>>(xin, wgt, bias, out);
}

// round 9
// speedup vs baseline: 4.3649x; 1.0679x over previous
#include <cuda_runtime.h>
#include <math.h>
#include <stdint.h>

// ---------------- problem constants ----------------
#define B_    32
#define CIN   512
#define H_    38
#define W_    38
#define P_    1444          // 38*38
#define NO_   255
#define NPAD  256
#define STRIDE_F 16.0f

// ---------------- tiling ----------------
#define TM      128         // pixels per CTA
#define TN      128         // out-channels per CTA (2 CTAs cover 256)
#define KC      32          // k per chunk
#define NCHUNK  (CIN / KC)  // 16
#define STAGES  3

// smem strides (floats) chosen for conflict-free access
#define A_LD    136         // A_sm[k][A_LD]; frag bank = t4*8+g (all distinct)
#define B_LD    36          // B_sm[n][B_LD]; frag bank = g*4+t4 (all distinct)
#define A_BYTES (KC * A_LD * 4)            // 17408
#define B_BYTES (TN * B_LD * 4)            // 18432
#define STAGE_BYTES (A_BYTES + B_BYTES)    // 35840
#define SMEM_TOTAL  (STAGE_BYTES * STAGES) // 107520 (2 CTAs / SM)

__constant__ float c_aw[3] = {30.0f, 62.0f, 59.0f};
__constant__ float c_ah[3] = {61.0f, 45.0f, 119.0f};

// tf32-converted, zero-padded weights [NPAD][CIN]
__device__ float g_wtf32[NPAD * CIN];

static __device__ __forceinline__ uint32_t smem_u32(const void* p) {
    uint32_t a;
    asm("{ .reg .u64 t; cvta.to.shared.u64 t, %1; cvt.u32.u64 %0, t; }" : "=r"(a) : "l"(p));
    return a;
}
static __device__ __forceinline__ uint32_t f2tf32(float f) {
    uint32_t r;
    asm("cvt.rna.tf32.f32 %0, %1;" : "=r"(r) : "f"(f));   // rna = unbiased rounding
    return r;
}
static __device__ __forceinline__ void cp_async16(uint32_t dst, const void* src) {
    asm volatile("cp.async.cg.shared.global [%0], [%1], 16;" :: "r"(dst), "l"(src));
}
#define CP_COMMIT() asm volatile("cp.async.commit_group;" ::: "memory")
#define CP_WAIT1()  asm volatile("cp.async.wait_group 1;" ::: "memory")

static __device__ __forceinline__ void mma_tf32(float c[4], const uint32_t a[4],
                                                const uint32_t b[2]) {
    asm volatile(
        "mma.sync.aligned.m16n8k8.row.col.f32.tf32.tf32.f32 "
        "{%0,%1,%2,%3}, {%4,%5,%6,%7}, {%8,%9}, {%0,%1,%2,%3};"
        : "+f"(c[0]), "+f"(c[1]), "+f"(c[2]), "+f"(c[3])
        : "r"(a[0]), "r"(a[1]), "r"(a[2]), "r"(a[3]), "r"(b[0]), "r"(b[1]));
}

// ---------------- pre-kernel: convert weights to tf32 (padded) ----------------
__global__ void cvt_wgt_kernel(const float* __restrict__ wgt)
{
    int i = blockIdx.x * blockDim.x + threadIdx.x;   // 0 .. NPAD*CIN-1
    int n = i >> 9;                                  // CIN = 512
    float v = (n < NO_) ? wgt[i] : 0.0f;             // i == n*512+k
    g_wtf32[i] = __uint_as_float(f2tf32(v));
}

__global__ __launch_bounds__(256, 2)
void yolo_mma_tf32(const float* __restrict__ xin,
                   const float* __restrict__ bias, float* __restrict__ out)
{
    extern __shared__ char smem[];
    const uint32_t sbase = smem_u32(smem);
    const int tid  = threadIdx.x;
    const int wid  = tid >> 5;
    const int lane = tid & 31;
    const int g    = lane >> 2;
    const int t4   = lane & 3;
    const int p0   = blockIdx.x * TM;
    const int n0   = blockIdx.y * TN;
    const int b    = blockIdx.z;
    const float* xb = xin + (size_t)b * CIN * P_;

    const int wm = (wid & 3) * 32;   // warp m base (4 m-groups)
    const int wn = (wid >> 2) * 64;  // warp n base (2 n-groups)

    float acc[2][8][4];
#pragma unroll
    for (int mt = 0; mt < 2; mt++)
#pragma unroll
        for (int nt = 0; nt < 8; nt++)
#pragma unroll
            for (int q = 0; q < 4; q++) acc[mt][nt][q] = 0.0f;

    // per-thread A-tile coordinates (one float4 row-segment per thread... 4 per thread)
    // A: 32 k-rows x 128 m  = 1024 float4; 256 threads x 4
    const int a_k  = tid >> 5;          // base k row (0..7), +8 per j
    const int a_m  = (tid & 31) * 4;    // m column
    const bool a_pred = (p0 + a_m) < P_;   // whole-float4 validity (P_=1444, %4==0)

    auto ldgA = [&](int chunk, float4 va[4]) {
        const int k0 = chunk * KC;
        const float* src = xb + (size_t)(k0 + a_k) * P_ + p0 + a_m;
#pragma unroll
        for (int j = 0; j < 4; j++) {
            va[j] = a_pred ? *reinterpret_cast<const float4*>(src + (size_t)(j * 8) * P_)
                           : make_float4(0.f, 0.f, 0.f, 0.f);
        }
    };
    auto stsA = [&](int stage, const float4 va[4]) {
        uint32_t base = sbase + stage * STAGE_BYTES + (uint32_t)(a_k * A_LD + a_m) * 4;
#pragma unroll
        for (int j = 0; j < 4; j++) {
            asm volatile("st.shared.v4.b32 [%0], {%1, %2, %3, %4};"
                         :: "r"(base + (uint32_t)(j * 8 * A_LD) * 4),
                            "r"(f2tf32(va[j].x)), "r"(f2tf32(va[j].y)),
                            "r"(f2tf32(va[j].z)), "r"(f2tf32(va[j].w)) : "memory");
        }
    };
    auto issueB = [&](int chunk, int stage) {
        const uint32_t bbase = sbase + stage * STAGE_BYTES + A_BYTES;
        const int k0 = chunk * KC;
        // 128 n-rows x 8 float4 = 1024 float4
#pragma unroll
        for (int j = 0; j < 4; j++) {
            int idx = tid + j * 256;
            int n = idx >> 3;
            int kq = (idx & 7) * 4;
            cp_async16(bbase + (uint32_t)(n * B_LD + kq) * 4,
                       g_wtf32 + (size_t)(n0 + n) * CIN + k0 + kq);
        }
    };

    // prologue: A chunks 0,1 staged+stored; B chunks 0,1 async
    {
        float4 va[4];
        ldgA(0, va); stsA(0, va);
        ldgA(1, va); stsA(1, va);
    }
    issueB(0, 0); CP_COMMIT();
    issueB(1, 1); CP_COMMIT();
    __syncthreads();   // A stores visible before first compute

    float4 va[4];
    for (int i = 0; i < NCHUNK; i++) {
        const int st = i % STAGES;
        const bool pre = (i + 2 < NCHUNK);
        if (pre) ldgA(i + 2, va);     // LDG early; completes during wait+barrier
        CP_WAIT1();                   // B_i resident
        __syncthreads();              // stage (i+2)%3 free; A_i stores visible
        if (pre) {
            stsA((i + 2) % STAGES, va);
            issueB(i + 2, (i + 2) % STAGES);
        }
        CP_COMMIT();                  // uniform group count

        const uint32_t* A  = (const uint32_t*)(smem + (size_t)st * STAGE_BYTES);
        const uint32_t* Bm = (const uint32_t*)(smem + (size_t)st * STAGE_BYTES + A_BYTES);

#pragma unroll
        for (int ks = 0; ks < 4; ks++) {
            const int kb = ks * 8;
            uint32_t af[2][4], bf[8][2];
#pragma unroll
            for (int mt = 0; mt < 2; mt++) {
                const int mb = wm + mt * 16;
                af[mt][0] = A[(kb + t4) * A_LD + mb + g];
                af[mt][1] = A[(kb + t4) * A_LD + mb + g + 8];
                af[mt][2] = A[(kb + t4 + 4) * A_LD + mb + g];
                af[mt][3] = A[(kb + t4 + 4) * A_LD + mb + g + 8];
            }
#pragma unroll
            for (int nt = 0; nt < 8; nt++) {
                const int nb = wn + nt * 8 + g;
                bf[nt][0] = Bm[nb * B_LD + kb + t4];
                bf[nt][1] = Bm[nb * B_LD + kb + t4 + 4];
            }
#pragma unroll
            for (int mt = 0; mt < 2; mt++)
#pragma unroll
                for (int nt = 0; nt < 8; nt++)
                    mma_tf32(acc[mt][nt], af[mt], bf[nt]);
        }
    }

    // ---------------- fused YOLO decode epilogue ----------------
#pragma unroll
    for (int mt = 0; mt < 2; mt++) {
        const int r0 = wm + mt * 16 + g;
#pragma unroll
        for (int half = 0; half < 2; half++) {
            const int p = p0 + r0 + half * 8;
            if (p >= P_) continue;
            const float xo = (float)(p % W_);
            const float yo = (float)(p / W_);
            const size_t obase = ((size_t)b * P_ + p) * NO_;
#pragma unroll
            for (int nt = 0; nt < 8; nt++) {
#pragma unroll
                for (int q = 0; q < 2; q++) {
                    const int o = n0 + wn + nt * 8 + t4 * 2 + q;
                    if (o >= NO_) continue;
                    float v = acc[mt][nt][half * 2 + q] + __ldg(bias + o);
                    const int ai = (o >= 170) ? 2 : ((o >= 85) ? 1 : 0);
                    const int e = o - ai * 85;
                    float res;
                    if (e >= 4)      res = v;
                    else if (e == 0) res = (1.0f / (1.0f + __expf(-v)) + xo) * STRIDE_F;
                    else if (e == 1) res = (1.0f / (1.0f + __expf(-v)) + yo) * STRIDE_F;
                    else if (e == 2) res = __expf(v) * c_aw[ai];
                    else             res = __expf(v) * c_ah[ai];
                    out[obase + o] = res;
                }
            }
        }
    }
}

extern "C" void kernel_launch(void* const* d_in, const int* in_sizes, int n_in,
                              void* d_out, int out_size)
{
    const float* xin  = (const float*)d_in[0];
    const float* wgt  = (const float*)d_in[1];
    const float* bias = (const float*)d_in[2];
    float* out = (float*)d_out;

    cudaFuncSetAttribute(yolo_mma_tf32, cudaFuncAttributeMaxDynamicSharedMemorySize,
                         SMEM_TOTAL);

    cvt_wgt_kernel<<<(NPAD * CIN) / 256, 256>>>(wgt);

    dim3 grid((P_ + TM - 1) / TM, 2, B_);   // 12 x 2 x 32 = 768 CTAs
    yolo_mma_tf32<<<grid, 256, SMEM_TOTAL>>>(xin, bias, out);
}

// round 10
// speedup vs baseline: 4.5359x; 1.0392x over previous
#include <cuda_runtime.h>
#include <math.h>
#include <stdint.h>

// ---------------- problem constants ----------------
#define B_    32
#define CIN   512
#define H_    38
#define W_    38
#define P_    1444          // 38*38
#define NO_   255
#define NPAD  256
#define STRIDE_F 16.0f

// ---------------- tiling ----------------
#define TM      128         // pixels per CTA
#define TN      128         // out-channels per CTA (2 CTAs cover 256)
#define KC      32          // k per chunk
#define NCHUNK  (CIN / KC)  // 16
#define STAGES  3

// A smem: [k][A_LD] floats, conflict-free fragment reads
#define A_LD    136
#define A_BYTES (KC * A_LD * 4)            // 17408
// B smem: pre-permuted fragment layout, exactly 128n x 32k words
#define B_BYTES (TN * KC * 4)              // 16384
#define STAGE_BYTES (A_BYTES + B_BYTES)    // 33792
#define SMEM_TOTAL  (STAGE_BYTES * STAGES) // 101376 (2 CTAs / SM)

__constant__ float c_aw[3] = {30.0f, 62.0f, 59.0f};
__constant__ float c_ah[3] = {61.0f, 45.0f, 119.0f};

// tf32-converted weights, permuted into MMA-fragment order:
// [n0Idx(2)][chunk(16)][wnIdx(2)][ks(4)][ntPair(4)][lane(32)][v(4)]
__device__ float g_wperm[NPAD * CIN];

static __device__ __forceinline__ uint32_t smem_u32(const void* p) {
    uint32_t a;
    asm("{ .reg .u64 t; cvta.to.shared.u64 t, %1; cvt.u32.u64 %0, t; }" : "=r"(a) : "l"(p));
    return a;
}
static __device__ __forceinline__ uint32_t f2tf32(float f) {
    uint32_t r;
    asm("cvt.rna.tf32.f32 %0, %1;" : "=r"(r) : "f"(f));   // rna = unbiased rounding
    return r;
}
static __device__ __forceinline__ void cp_async16(uint32_t dst, const void* src) {
    asm volatile("cp.async.cg.shared.global [%0], [%1], 16;" :: "r"(dst), "l"(src));
}
#define CP_COMMIT() asm volatile("cp.async.commit_group;" ::: "memory")
#define CP_WAIT1()  asm volatile("cp.async.wait_group 1;" ::: "memory")

static __device__ __forceinline__ void mma_tf32(float c[4], const uint32_t a[4],
                                                uint32_t b0, uint32_t b1) {
    asm volatile(
        "mma.sync.aligned.m16n8k8.row.col.f32.tf32.tf32.f32 "
        "{%0,%1,%2,%3}, {%4,%5,%6,%7}, {%8,%9}, {%0,%1,%2,%3};"
        : "+f"(c[0]), "+f"(c[1]), "+f"(c[2]), "+f"(c[3])
        : "r"(a[0]), "r"(a[1]), "r"(a[2]), "r"(a[3]), "r"(b0), "r"(b1));
}

// ---------------- pre-kernel: convert + permute weights ----------------
__global__ void cvt_wgt_kernel(const float* __restrict__ wgt)
{
    int i = blockIdx.x * blockDim.x + threadIdx.x;   // 0 .. NPAD*CIN-1
    // decompose destination index
    int v      = i & 3;
    int lane   = (i >> 2) & 31;
    int ntp    = (i >> 7) & 3;
    int ks     = (i >> 9) & 3;
    int wnIdx  = (i >> 11) & 1;
    int chunk  = (i >> 12) & 15;
    int n0Idx  = i >> 16;
    // source (n, k):  v = {bf[2ntp][0], bf[2ntp][1], bf[2ntp+1][0], bf[2ntp+1][1]}
    int n = n0Idx * 128 + wnIdx * 64 + (ntp * 2 + (v >> 1)) * 8 + (lane >> 2);
    int k = chunk * 32 + ks * 8 + (lane & 3) + 4 * (v & 1);
    float val = (n < NO_) ? wgt[n * CIN + k] : 0.0f;
    g_wperm[i] = __uint_as_float(f2tf32(val));
}

__global__ __launch_bounds__(256, 2)
void yolo_mma_tf32(const float* __restrict__ xin,
                   const float* __restrict__ bias, float* __restrict__ out)
{
    extern __shared__ char smem[];
    const uint32_t sbase = smem_u32(smem);
    const int tid  = threadIdx.x;
    const int wid  = tid >> 5;
    const int lane = tid & 31;
    const int g    = lane >> 2;
    const int t4   = lane & 3;
    const int p0   = blockIdx.x * TM;
    const int n0   = blockIdx.y * TN;
    const int b    = blockIdx.z;
    const float* xb = xin + (size_t)b * CIN * P_;

    const int wm    = (wid & 3) * 32;   // warp m base (4 m-groups)
    const int wnIdx = wid >> 2;         // warp n group (0/1)

    float acc[2][8][4];
#pragma unroll
    for (int mt = 0; mt < 2; mt++)
#pragma unroll
        for (int nt = 0; nt < 8; nt++)
#pragma unroll
            for (int q = 0; q < 4; q++) acc[mt][nt][q] = 0.0f;

    // per-thread A-tile coordinates: 32 k-rows x 128 m = 1024 float4; 4 per thread
    const int a_k  = tid >> 5;          // base k row (0..7), +8 per j
    const int a_m  = (tid & 31) * 4;    // m column
    const bool a_pred = (p0 + a_m) < P_;

    auto ldgA = [&](int chunk, float4 va[4]) {
        const int k0 = chunk * KC;
        const float* src = xb + (size_t)(k0 + a_k) * P_ + p0 + a_m;
#pragma unroll
        for (int j = 0; j < 4; j++) {
            va[j] = a_pred ? *reinterpret_cast<const float4*>(src + (size_t)(j * 8) * P_)
                           : make_float4(0.f, 0.f, 0.f, 0.f);
        }
    };
    auto stsA = [&](int stage, const float4 va[4]) {
        uint32_t base = sbase + stage * STAGE_BYTES + (uint32_t)(a_k * A_LD + a_m) * 4;
#pragma unroll
        for (int j = 0; j < 4; j++) {
            asm volatile("st.shared.v4.b32 [%0], {%1, %2, %3, %4};"
                         :: "r"(base + (uint32_t)(j * 8 * A_LD) * 4),
                            "r"(f2tf32(va[j].x)), "r"(f2tf32(va[j].y)),
                            "r"(f2tf32(va[j].z)), "r"(f2tf32(va[j].w)) : "memory");
        }
    };
    // B: linear 16KB copy (permutation pre-baked in gmem)
    const float* wsrc = g_wperm + (size_t)(blockIdx.y * 16) * (TN * KC);
    auto issueB = [&](int chunk, int stage) {
        const uint32_t bbase = sbase + stage * STAGE_BYTES + A_BYTES;
        const float* src = wsrc + (size_t)chunk * (TN * KC);
#pragma unroll
        for (int j = 0; j < 4; j++) {
            int idx = tid + j * 256;     // 0..1023 float4
            cp_async16(bbase + (uint32_t)idx * 16, src + (size_t)idx * 4);
        }
    };

    // prologue
    {
        float4 va[4];
        ldgA(0, va); stsA(0, va);
        ldgA(1, va); stsA(1, va);
    }
    issueB(0, 0); CP_COMMIT();
    issueB(1, 1); CP_COMMIT();
    __syncthreads();

    float4 va[4];
    for (int i = 0; i < NCHUNK; i++) {
        const int st = i % STAGES;
        const bool pre = (i + 2 < NCHUNK);
        if (pre) ldgA(i + 2, va);
        CP_WAIT1();
        __syncthreads();
        if (pre) {
            stsA((i + 2) % STAGES, va);
            issueB(i + 2, (i + 2) % STAGES);
        }
        CP_COMMIT();

        const uint32_t* A  = (const uint32_t*)(smem + (size_t)st * STAGE_BYTES);
        const uint4*    Bv = (const uint4*)(smem + (size_t)st * STAGE_BYTES + A_BYTES);

#pragma unroll
        for (int ks = 0; ks < 4; ks++) {
            const int kb = ks * 8;
            uint32_t af[2][4];
#pragma unroll
            for (int mt = 0; mt < 2; mt++) {
                const int mb = wm + mt * 16;
                af[mt][0] = A[(kb + t4) * A_LD + mb + g];
                af[mt][1] = A[(kb + t4) * A_LD + mb + g + 8];
                af[mt][2] = A[(kb + t4 + 4) * A_LD + mb + g];
                af[mt][3] = A[(kb + t4 + 4) * A_LD + mb + g + 8];
            }
            // B fragment: 4 x LDS.128, lane-consecutive (conflict-free)
            const int bbase = (wnIdx * 4 + ks) * 128 + lane;   // uint4 index
#pragma unroll
            for (int ntp = 0; ntp < 4; ntp++) {
                uint4 q = Bv[bbase + ntp * 32];
#pragma unroll
                for (int mt = 0; mt < 2; mt++) {
                    mma_tf32(acc[mt][ntp * 2 + 0], af[mt], q.x, q.y);
                    mma_tf32(acc[mt][ntp * 2 + 1], af[mt], q.z, q.w);
                }
            }
        }
    }

    // ---------------- fused YOLO decode epilogue ----------------
    const int wn = wnIdx * 64;
#pragma unroll
    for (int mt = 0; mt < 2; mt++) {
        const int r0 = wm + mt * 16 + g;
#pragma unroll
        for (int half = 0; half < 2; half++) {
            const int p = p0 + r0 + half * 8;
            if (p >= P_) continue;
            const float xo = (float)(p % W_);
            const float yo = (float)(p / W_);
            const size_t obase = ((size_t)b * P_ + p) * NO_;
#pragma unroll
            for (int nt = 0; nt < 8; nt++) {
#pragma unroll
                for (int q = 0; q < 2; q++) {
                    const int o = n0 + wn + nt * 8 + t4 * 2 + q;
                    if (o >= NO_) continue;
                    float v = acc[mt][nt][half * 2 + q] + __ldg(bias + o);
                    const int ai = (o >= 170) ? 2 : ((o >= 85) ? 1 : 0);
                    const int e = o - ai * 85;
                    float res;
                    if (e >= 4)      res = v;
                    else if (e == 0) res = (1.0f / (1.0f + __expf(-v)) + xo) * STRIDE_F;
                    else if (e == 1) res = (1.0f / (1.0f + __expf(-v)) + yo) * STRIDE_F;
                    else if (e == 2) res = __expf(v) * c_aw[ai];
                    else             res = __expf(v) * c_ah[ai];
                    out[obase + o] = res;
                }
            }
        }
    }
}

extern "C" void kernel_launch(void* const* d_in, const int* in_sizes, int n_in,
                              void* d_out, int out_size)
{
    const float* xin  = (const float*)d_in[0];
    const float* wgt  = (const float*)d_in[1];
    const float* bias = (const float*)d_in[2];
    float* out = (float*)d_out;

    cudaFuncSetAttribute(yolo_mma_tf32, cudaFuncAttributeMaxDynamicSharedMemorySize,
                         SMEM_TOTAL);

    cvt_wgt_kernel<<<(NPAD * CIN) / 256, 256>>>(wgt);

    dim3 grid((P_ + TM - 1) / TM, 2, B_);   // 12 x 2 x 32 = 768 CTAs
    yolo_mma_tf32<<<grid, 256, SMEM_TOTAL>>>(xin, bias, out);
}

// round 14
// speedup vs baseline: 6.1198x; 1.3492x over previous
#include <cuda_runtime.h>
#include <math.h>
#include <stdint.h>

// ---------------- problem constants ----------------
#define B_    32
#define CIN   512
#define H_    38
#define W_    38
#define P_    1444          // 38*38
#define NO_   255
#define NPAD  256
#define STRIDE_F 16.0f

// ---------------- tiling ----------------
#define TM      128         // pixels per CTA
#define TN      128         // out-channels per CTA
#define KC      32          // k per chunk
#define NCHUNK  (CIN / KC)  // 16
#define STAGES  3

// A smem: V[k2(16)][m(128)] bf16x2, row stride 136 words (conflict-free frags)
#define A_LDW   136
#define A_BYTES (16 * A_LDW * 4)           // 8704
// B smem: pre-permuted fragment layout, 2 ksteps * 4 ntp * 32 lanes * 16B * 2 wn
#define B_BYTES (TN * KC * 2)              // 8192
#define STAGE_BYTES (A_BYTES + B_BYTES)    // 16896
#define SMEM_TOTAL  (STAGE_BYTES * STAGES) // 50688 (2 CTAs/SM easily)

__constant__ float c_aw[3] = {30.0f, 62.0f, 59.0f};
__constant__ float c_ah[3] = {61.0f, 45.0f, 119.0f};

// bf16 weights permuted into m16n8k16 B-fragment order:
// [n0Idx(2)][chunk(16)][wnIdx(2)][kst(2)][ntp(4)][lane(32)][v(4 uint32)]
__device__ uint32_t g_wperm[NPAD * CIN / 2];

static __device__ __forceinline__ uint32_t smem_u32(const void* p) {
    uint32_t a;
    asm("{ .reg .u64 t; cvta.to.shared.u64 t, %1; cvt.u32.u64 %0, t; }" : "=r"(a) : "l"(p));
    return a;
}
// pack {lo=a, hi=b} as bf16x2 (round-nearest)
static __device__ __forceinline__ uint32_t pack_bf16x2(float lo, float hi) {
    uint32_t r;
    asm("cvt.rn.bf16x2.f32 %0, %1, %2;" : "=r"(r) : "f"(hi), "f"(lo));
    return r;
}
static __device__ __forceinline__ void cp_async16(uint32_t dst, const void* src) {
    asm volatile("cp.async.cg.shared.global [%0], [%1], 16;" :: "r"(dst), "l"(src));
}
#define CP_COMMIT() asm volatile("cp.async.commit_group;" ::: "memory")
#define CP_WAIT1()  asm volatile("cp.async.wait_group 1;" ::: "memory")

static __device__ __forceinline__ void mma_bf16(float c[4], const uint32_t a[4],
                                                uint32_t b0, uint32_t b1) {
    asm volatile(
        "mma.sync.aligned.m16n8k16.row.col.f32.bf16.bf16.f32 "
        "{%0,%1,%2,%3}, {%4,%5,%6,%7}, {%8,%9}, {%0,%1,%2,%3};"
        : "+f"(c[0]), "+f"(c[1]), "+f"(c[2]), "+f"(c[3])
        : "r"(a[0]), "r"(a[1]), "r"(a[2]), "r"(a[3]), "r"(b0), "r"(b1));
}

// ---------------- pre-kernel: convert + permute weights to bf16 frags ----------------
__global__ void cvt_wgt_kernel(const float* __restrict__ wgt)
{
    int i = blockIdx.x * blockDim.x + threadIdx.x;   // 0 .. 65535 (uint32 slots)
    int v     = i & 3;
    int lane  = (i >> 2) & 31;
    int ntp   = (i >> 7) & 3;
    int kst   = (i >> 9) & 1;
    int wnIdx = (i >> 10) & 1;
    int chunk = (i >> 11) & 15;
    int n0Idx = i >> 15;
    int g  = lane >> 2;
    int t4 = lane & 3;
    int nt  = 2 * ntp + (v >> 1);
    int reg = v & 1;                                  // b0 / b1
    int n = n0Idx * 128 + wnIdx * 64 + nt * 8 + g;
    int k = chunk * 32 + kst * 16 + 2 * t4 + 8 * reg;
    float v0 = (n < NO_) ? wgt[n * CIN + k]     : 0.0f;
    float v1 = (n < NO_) ? wgt[n * CIN + k + 1] : 0.0f;
    g_wperm[i] = pack_bf16x2(v0, v1);                 // lo = k, hi = k+1
}

__global__ __launch_bounds__(256, 2)
void yolo_mma_bf16(const float* __restrict__ xin,
                   const float* __restrict__ bias, float* __restrict__ out)
{
    extern __shared__ char smem[];
    const uint32_t sbase = smem_u32(smem);
    const int tid  = threadIdx.x;
    const int wid  = tid >> 5;
    const int lane = tid & 31;
    const int g    = lane >> 2;
    const int t4   = lane & 3;
    const int p0   = blockIdx.x * TM;
    const int n0   = blockIdx.y * TN;
    const int b    = blockIdx.z;
    const float* xb = xin + (size_t)b * CIN * P_;

    const int wm    = (wid & 3) * 32;   // warp m base (4 m-groups)
    const int wnIdx = wid >> 2;         // warp n group (0/1)

    float acc[2][8][4];
#pragma unroll
    for (int mt = 0; mt < 2; mt++)
#pragma unroll
        for (int nt = 0; nt < 8; nt++)
#pragma unroll
            for (int q = 0; q < 4; q++) acc[mt][nt][q] = 0.0f;

    // A loader: thread handles k-rows (r, r+1) and (r+16, r+17) at m-slot m4
    const int a_r  = 2 * (tid >> 5);    // 0..14 even
    const int a_m4 = tid & 31;          // float4 column (m = 4*a_m4)
    const bool a_pred = (p0 + a_m4 * 4) < P_;

    auto ldgA = [&](int chunk, float4 va[4]) {
        const int k0 = chunk * KC;
        const float* s0 = xb + (size_t)(k0 + a_r) * P_ + p0 + a_m4 * 4;
        if (a_pred) {
            va[0] = *reinterpret_cast<const float4*>(s0);
            va[1] = *reinterpret_cast<const float4*>(s0 + P_);
            va[2] = *reinterpret_cast<const float4*>(s0 + (size_t)16 * P_);
            va[3] = *reinterpret_cast<const float4*>(s0 + (size_t)17 * P_);
        } else {
            va[0] = va[1] = va[2] = va[3] = make_float4(0.f, 0.f, 0.f, 0.f);
        }
    };
    auto stsA = [&](int stage, const float4 va[4]) {
        const uint32_t base = sbase + stage * STAGE_BYTES;
        const int k2a = a_r >> 1;       // 0..7
        uint32_t w0 = pack_bf16x2(va[0].x, va[1].x), w1 = pack_bf16x2(va[0].y, va[1].y);
        uint32_t w2 = pack_bf16x2(va[0].z, va[1].z), w3 = pack_bf16x2(va[0].w, va[1].w);
        asm volatile("st.shared.v4.b32 [%0], {%1, %2, %3, %4};"
                     :: "r"(base + (uint32_t)(k2a * A_LDW + a_m4 * 4) * 4),
                        "r"(w0), "r"(w1), "r"(w2), "r"(w3) : "memory");
        w0 = pack_bf16x2(va[2].x, va[3].x); w1 = pack_bf16x2(va[2].y, va[3].y);
        w2 = pack_bf16x2(va[2].z, va[3].z); w3 = pack_bf16x2(va[2].w, va[3].w);
        asm volatile("st.shared.v4.b32 [%0], {%1, %2, %3, %4};"
                     :: "r"(base + (uint32_t)((k2a + 8) * A_LDW + a_m4 * 4) * 4),
                        "r"(w0), "r"(w1), "r"(w2), "r"(w3) : "memory");
    };
    // B: linear 8KB copy of pre-permuted fragment data
    const uint32_t* wsrc = g_wperm + (size_t)blockIdx.y * 32768;
    auto issueB = [&](int chunk, int stage) {
        const uint32_t bbase = sbase + stage * STAGE_BYTES + A_BYTES;
        const uint32_t* src = wsrc + (size_t)chunk * 2048;
#pragma unroll
        for (int j = 0; j < 2; j++) {
            int idx = tid + j * 256;     // 0..511 uint4
            cp_async16(bbase + (uint32_t)idx * 16, src + (size_t)idx * 4);
        }
    };

    // prologue
    {
        float4 va[4];
        ldgA(0, va); stsA(0, va);
        ldgA(1, va); stsA(1, va);
    }
    issueB(0, 0); CP_COMMIT();
    issueB(1, 1); CP_COMMIT();
    __syncthreads();

    float4 va[4];
    for (int i = 0; i < NCHUNK; i++) {
        const int st = i % STAGES;
        const bool pre = (i + 2 < NCHUNK);
        if (pre) ldgA(i + 2, va);
        CP_WAIT1();
        __syncthreads();
        if (pre) {
            stsA((i + 2) % STAGES, va);
            issueB(i + 2, (i + 2) % STAGES);
        }
        CP_COMMIT();

        const uint32_t* V  = (const uint32_t*)(smem + (size_t)st * STAGE_BYTES);
        const uint4*    Bv = (const uint4*)(smem + (size_t)st * STAGE_BYTES + A_BYTES);

#pragma unroll
        for (int kst = 0; kst < 2; kst++) {          // two k16 steps per chunk
            const int kb2 = kst * 8;
            uint32_t af[2][4];
#pragma unroll
            for (int mt = 0; mt < 2; mt++) {
                const int mb = wm + mt * 16 + g;
                af[mt][0] = V[(kb2 + t4) * A_LDW + mb];
                af[mt][1] = V[(kb2 + t4) * A_LDW + mb + 8];
                af[mt][2] = V[(kb2 + t4 + 4) * A_LDW + mb];
                af[mt][3] = V[(kb2 + t4 + 4) * A_LDW + mb + 8];
            }
            const int bbase = (wnIdx * 2 + kst) * 128 + lane;   // uint4 index
#pragma unroll
            for (int ntp = 0; ntp < 4; ntp++) {
                uint4 q = Bv[bbase + ntp * 32];
#pragma unroll
                for (int mt = 0; mt < 2; mt++) {
                    mma_bf16(acc[mt][ntp * 2 + 0], af[mt], q.x, q.y);
                    mma_bf16(acc[mt][ntp * 2 + 1], af[mt], q.z, q.w);
                }
            }
        }
    }

    // ---------------- fused YOLO decode epilogue ----------------
    const int wn = wnIdx * 64;
#pragma unroll
    for (int mt = 0; mt < 2; mt++) {
        const int r0 = wm + mt * 16 + g;
#pragma unroll
        for (int half = 0; half < 2; half++) {
            const int p = p0 + r0 + half * 8;
            if (p >= P_) continue;
            const float xo = (float)(p % W_);
            const float yo = (float)(p / W_);
            const size_t obase = ((size_t)b * P_ + p) * NO_;
#pragma unroll
            for (int nt = 0; nt < 8; nt++) {
#pragma unroll
                for (int q = 0; q < 2; q++) {
                    const int o = n0 + wn + nt * 8 + t4 * 2 + q;
                    if (o >= NO_) continue;
                    float v = acc[mt][nt][half * 2 + q] + __ldg(bias + o);
                    const int ai = (o >= 170) ? 2 : ((o >= 85) ? 1 : 0);
                    const int e = o - ai * 85;
                    float res;
                    if (e >= 4)      res = v;
                    else if (e == 0) res = (1.0f / (1.0f + __expf(-v)) + xo) * STRIDE_F;
                    else if (e == 1) res = (1.0f / (1.0f + __expf(-v)) + yo) * STRIDE_F;
                    else if (e == 2) res = __expf(v) * c_aw[ai];
                    else             res = __expf(v) * c_ah[ai];
                    out[obase + o] = res;
                }
            }
        }
    }
}

extern "C" void kernel_launch(void* const* d_in, const int* in_sizes, int n_in,
                              void* d_out, int out_size)
{
    const float* xin  = (const float*)d_in[0];
    const float* wgt  = (const float*)d_in[1];
    const float* bias = (const float*)d_in[2];
    float* out = (float*)d_out;

    cudaFuncSetAttribute(yolo_mma_bf16, cudaFuncAttributeMaxDynamicSharedMemorySize,
                         SMEM_TOTAL);

    cvt_wgt_kernel<<<(NPAD * CIN / 2) / 256, 256>>>(wgt);

    dim3 grid((P_ + TM - 1) / TM, 2, B_);   // 12 x 2 x 32 = 768 CTAs
    yolo_mma_bf16<<<grid, 256, SMEM_TOTAL>>>(xin, bias, out);
}